// round 16
// baseline (speedup 1.0000x reference)
#include <cuda_runtime.h>
#include <cuda_bf16.h>
#include <cuda_fp16.h>
#include <math.h>
#include <stdint.h>

// ---------------------------------------------------------------------------
// Problem constants
// ---------------------------------------------------------------------------
#define NN 100000
#define EE 3200000
#define F0 512
#define F1 256
#define F2 256
#define F3 64

// ---------------------------------------------------------------------------
// Scratch (__device__ globals; no allocations allowed)
// ---------------------------------------------------------------------------
__device__ uint32_t g_S8 [(size_t)NN * 64];    // fp8(e4m3) support, F=256 (25.6 MB)
__device__ uint32_t g_Hbf[(size_t)NN * 128];   // bf16x2 activations, F=256 (51.2 MB)
__device__ uint16_t g_C8 [(size_t)NN * 32];    // fp8x2 support, F=64 (6.4 MB)
__device__ uint16_t g_W1t[F1 * F0];            // Wt[N][K] bf16 (transposed)
__device__ uint16_t g_W2t[F2 * F1];
__device__ uint16_t g_W3t[F3 * F2];
__device__ int      g_rowptr[NN + 1];
__device__ int      g_cursor[NN];
__device__ int2     g_edge[EE];                // packed (col, val-bits)
__device__ int      g_bsums[128];

// bf16x2 -> two fp32 (exact, pure ALU)
__device__ __forceinline__ float2 bf2x_to_f2(uint32_t u) {
    float2 f;
    f.x = __uint_as_float(u << 16);
    f.y = __uint_as_float(u & 0xffff0000u);
    return f;
}
// 2x e4m3 (packed u16) -> float2 via half2
__device__ __forceinline__ float2 fp8x2_to_f2(uint16_t p) {
    uint32_t h;
    asm("cvt.rn.f16x2.e4m3x2 %0, %1;" : "=r"(h) : "h"(p));
    return __half22float2(*(__half2*)&h);
}
__device__ __forceinline__ uint16_t f2_to_fp8x2(float lo, float hi) {
    uint16_t p;
    asm("cvt.rn.satfinite.e4m3x2.f32 %0, %1, %2;" : "=h"(p) : "f"(hi), "f"(lo));
    return p;  // low byte = lo
}
__device__ __forceinline__ uint32_t f2_to_bf2x(float lo, float hi) {
    __nv_bfloat162 p = __floats2bfloat162_rn(lo, hi);
    return *(uint32_t*)&p;
}

// ---------------------------------------------------------------------------
// Weight conversion: W[K][N] fp32 -> Wt[N][K] bf16
// ---------------------------------------------------------------------------
__global__ void k_cvt_wt(const float* __restrict__ W, uint16_t* __restrict__ Wt, int K, int N) {
    int i = blockIdx.x * blockDim.x + threadIdx.x;
    if (i < K * N) {
        int k = i / N, n = i % N;
        __nv_bfloat16 b = __float2bfloat16(W[i]);
        Wt[(size_t)n * K + k] = *(uint16_t*)&b;
    }
}

// ---------------------------------------------------------------------------
// CSR build: histogram -> exclusive scan -> scatter (packed records)
// ---------------------------------------------------------------------------
__global__ void k_zero_int(int* p, int n) {
    int i = blockIdx.x * blockDim.x + threadIdx.x;
    if (i < n) p[i] = 0;
}

__global__ void k_hist(const int* __restrict__ erow) {
    int e = blockIdx.x * blockDim.x + threadIdx.x;
    if (e < EE) atomicAdd(&g_cursor[erow[e]], 1);
}

__global__ void k_scan_block(int n) {
    int tid  = threadIdx.x;
    int i    = blockIdx.x * 1024 + tid;
    int v    = (i < NN) ? g_cursor[i] : 0;
    int lane = tid & 31, warp = tid >> 5;
    int x = v;
    #pragma unroll
    for (int o = 1; o < 32; o <<= 1) {
        int y = __shfl_up_sync(0xFFFFFFFFu, x, o);
        if (lane >= o) x += y;
    }
    __shared__ int wsum[32];
    if (lane == 31) wsum[warp] = x;
    __syncthreads();
    if (warp == 0) {
        int w = wsum[lane];
        #pragma unroll
        for (int o = 1; o < 32; o <<= 1) {
            int y = __shfl_up_sync(0xFFFFFFFFu, w, o);
            if (lane >= o) w += y;
        }
        wsum[lane] = w;
    }
    __syncthreads();
    int incl = x + (warp > 0 ? wsum[warp - 1] : 0);
    if (i < n) g_rowptr[i] = incl - v;
    if (tid == 1023) g_bsums[blockIdx.x] = incl;
}

__global__ void k_scan_spine(int nb) {
    int tid = threadIdx.x;
    int lane = tid & 31, warp = tid >> 5;
    int v = (tid < nb) ? g_bsums[tid] : 0;
    int x = v;
    #pragma unroll
    for (int o = 1; o < 32; o <<= 1) {
        int y = __shfl_up_sync(0xFFFFFFFFu, x, o);
        if (lane >= o) x += y;
    }
    __shared__ int ws[4];
    if (lane == 31) ws[warp] = x;
    __syncthreads();
    int off = 0;
    for (int w = 0; w < warp; w++) off += ws[w];
    if (tid < nb) g_bsums[tid] = (x + off) - v;
}

// adds block offsets; also seeds cursor = rowptr for the scatter pass
__global__ void k_scan_add(int n) {
    int i = blockIdx.x * 1024 + threadIdx.x;
    if (i < n) {
        int v = g_rowptr[i] + g_bsums[blockIdx.x];
        g_rowptr[i] = v;
        if (i < NN) g_cursor[i] = v;
    }
}

__global__ void k_scatter(const int* __restrict__ erow,
                          const int* __restrict__ ecol,
                          const float* __restrict__ eval) {
    int e = blockIdx.x * blockDim.x + threadIdx.x;
    if (e < EE) {
        int r = erow[e];
        int p = atomicAdd(&g_cursor[r], 1);
        int2 rec;
        rec.x = ecol[e];
        rec.y = __float_as_int(eval[e]);
        g_edge[p] = rec;
    }
}

// ---------------------------------------------------------------------------
// GEMM1: C = fp8( A_fp32[M,K] @ Wt[N,K]^T ), A converted to bf16 in-register.
// 128x128 tile, 4 warps (64x64 each), BK=16, cp.async.cg double-buffered.
// ---------------------------------------------------------------------------
__global__ __launch_bounds__(128) void k_gemm_f32a(
    const float* __restrict__ A, const uint16_t* __restrict__ Wt,
    uint16_t* __restrict__ C8, int M, int N, int K)
{
    constexpr int BM = 128, BN = 128, BK = 16;
    constexpr int NT = 128;
    constexpr int ASTF = BK + 8;   // 24 floats  (LDS.64 conflict-free)
    constexpr int BST  = BK + 8;   // 24 bf16
    constexpr int MT = 4, NTL = 8;

    __shared__ __align__(16) float    Asf[2][BM][ASTF];
    __shared__ __align__(16) uint16_t Bs [2][BN][BST];

    const int tid = threadIdx.x;
    const int lane = tid & 31, wid = tid >> 5;
    const int wm = (wid % 2) * 64;
    const int wn = (wid / 2) * 64;
    const int m0 = blockIdx.y * BM, n0 = blockIdx.x * BN;

    float acc[MT][NTL][4];
    #pragma unroll
    for (int i = 0; i < MT; i++)
        #pragma unroll
        for (int j = 0; j < NTL; j++)
            #pragma unroll
            for (int q = 0; q < 4; q++) acc[i][j][q] = 0.f;

    const int T = K / BK;

    #define ISSUE1(t, buf)                                                      \
    {                                                                           \
        int k0 = (t) * BK;                                                      \
        _Pragma("unroll")                                                       \
        for (int j = 0; j < 4; j++) {          /* A: 128x16 fp32, 4 f4/thr */   \
            int f = tid + j * NT;                                               \
            int m = f >> 2, c = (f & 3) << 2;                                   \
            int gm = m0 + m;                                                    \
            const float* src = A + (size_t)(gm < M ? gm : 0) * K + k0 + c;      \
            uint32_t dst = (uint32_t)__cvta_generic_to_shared(&Asf[buf][m][c]); \
            int sz = (gm < M) ? 16 : 0;                                         \
            asm volatile("cp.async.cg.shared.global [%0], [%1], 16, %2;\n"      \
                         :: "r"(dst), "l"(src), "r"(sz));                       \
        }                                                                       \
        _Pragma("unroll")                                                       \
        for (int j = 0; j < 2; j++) {          /* B: 128x16 bf16, 2 16B/thr */  \
            int f = tid + j * NT;                                               \
            int n = f >> 1, c = (f & 1) << 3;                                   \
            const uint16_t* src = Wt + (size_t)(n0 + n) * K + k0 + c;           \
            uint32_t dst = (uint32_t)__cvta_generic_to_shared(&Bs[buf][n][c]);  \
            asm volatile("cp.async.cg.shared.global [%0], [%1], 16;\n"          \
                         :: "r"(dst), "l"(src));                                \
        }                                                                       \
        asm volatile("cp.async.commit_group;\n");                               \
    }

    ISSUE1(0, 0);
    ISSUE1(1, 1);
    asm volatile("cp.async.wait_group 1;\n");
    __syncthreads();

    const int r  = lane >> 2;
    const int c0 = (lane & 3) * 2;

    for (int t = 0; t < T; t++) {
        const int buf = t & 1;
        uint32_t af[MT][4];
        #pragma unroll
        for (int mt = 0; mt < MT; mt++) {
            float2 p0 = *(const float2*)&Asf[buf][wm + mt*16 + r    ][c0    ];
            float2 p1 = *(const float2*)&Asf[buf][wm + mt*16 + r + 8][c0    ];
            float2 p2 = *(const float2*)&Asf[buf][wm + mt*16 + r    ][c0 + 8];
            float2 p3 = *(const float2*)&Asf[buf][wm + mt*16 + r + 8][c0 + 8];
            af[mt][0] = f2_to_bf2x(p0.x, p0.y);
            af[mt][1] = f2_to_bf2x(p1.x, p1.y);
            af[mt][2] = f2_to_bf2x(p2.x, p2.y);
            af[mt][3] = f2_to_bf2x(p3.x, p3.y);
        }
        #pragma unroll
        for (int nt = 0; nt < NTL; nt++) {
            const uint16_t* pb = &Bs[buf][wn + nt*8 + r][c0];
            uint32_t b0 = *(const uint32_t*)pb;
            uint32_t b1 = *(const uint32_t*)(pb + 8);
            #pragma unroll
            for (int mt = 0; mt < MT; mt++) {
                asm volatile(
                    "mma.sync.aligned.m16n8k16.row.col.f32.bf16.bf16.f32 "
                    "{%0,%1,%2,%3},{%4,%5,%6,%7},{%8,%9},{%0,%1,%2,%3};\n"
                    : "+f"(acc[mt][nt][0]), "+f"(acc[mt][nt][1]),
                      "+f"(acc[mt][nt][2]), "+f"(acc[mt][nt][3])
                    : "r"(af[mt][0]), "r"(af[mt][1]),
                      "r"(af[mt][2]), "r"(af[mt][3]),
                      "r"(b0), "r"(b1));
            }
        }
        __syncthreads();
        if (t + 2 < T) { ISSUE1(t + 2, buf); }
        else           { asm volatile("cp.async.commit_group;\n"); }
        asm volatile("cp.async.wait_group 1;\n");
        __syncthreads();
    }
    #undef ISSUE1

    #pragma unroll
    for (int mt = 0; mt < MT; mt++) {
        int r0 = m0 + wm + mt*16 + r;
        #pragma unroll
        for (int nt = 0; nt < NTL; nt++) {
            int cc = n0 + wn + nt*8 + c0;
            if (r0 < M)
                C8[(size_t)r0 * (N/2) + cc/2] =
                    f2_to_fp8x2(acc[mt][nt][0], acc[mt][nt][1]);
            if (r0 + 8 < M)
                C8[(size_t)(r0 + 8) * (N/2) + cc/2] =
                    f2_to_fp8x2(acc[mt][nt][2], acc[mt][nt][3]);
        }
    }
}

// ---------------------------------------------------------------------------
// BF16 tensor-core GEMM: C[M,N] = A[M,K] @ Wt[N,K]^T  (A already bf16)
// mma.sync.m16n8k16.bf16, cp.async.cg double-buffered, 80B-stride.
// OUT: 1 = bf16x2 packed, 2 = e4m3 packed.
// ---------------------------------------------------------------------------
template<int BM, int BN, int WM, int WN, int OUT>
__global__ __launch_bounds__((BM/WM)*(BN/WN)*32) void k_gemm_bf(
    const uint16_t* __restrict__ A, const uint16_t* __restrict__ Wt,
    void* __restrict__ Cv, int M, int N, int K)
{
    constexpr int BK  = 32;
    constexpr int NWARP = (BM/WM)*(BN/WN);
    constexpr int NT  = NWARP * 32;
    constexpr int ST  = BK + 8;            // 40 bf16 = 80 B row stride
    constexpr int ACH = BM*BK/8/NT;
    constexpr int BCH = BN*BK/8/NT;
    constexpr int MT  = WM/16, NTL = WN/8;

    __shared__ uint16_t As[2][BM][ST];
    __shared__ uint16_t Bs[2][BN][ST];

    const int tid  = threadIdx.x;
    const int lane = tid & 31, wid = tid >> 5;
    const int wm   = (wid % (BM/WM)) * WM;
    const int wn   = (wid / (BM/WM)) * WN;
    const int m0   = blockIdx.y * BM, n0 = blockIdx.x * BN;

    float acc[MT][NTL][4];
    #pragma unroll
    for (int i = 0; i < MT; i++)
        #pragma unroll
        for (int j = 0; j < NTL; j++)
            #pragma unroll
            for (int q = 0; q < 4; q++) acc[i][j][q] = 0.f;

    const int T = K / BK;

    #define ISSUE(t, buf)                                                       \
    {                                                                           \
        int k0 = (t) * BK;                                                      \
        _Pragma("unroll")                                                       \
        for (int j = 0; j < ACH; j++) {                                         \
            int f = tid + j * NT;                                               \
            int m = f >> 2, c = (f & 3) << 3;                                   \
            int gm = m0 + m;                                                    \
            const uint16_t* src = A + (size_t)(gm < M ? gm : 0) * K + k0 + c;   \
            uint32_t dst = (uint32_t)__cvta_generic_to_shared(&As[buf][m][c]);  \
            int sz = (gm < M) ? 16 : 0;                                         \
            asm volatile("cp.async.cg.shared.global [%0], [%1], 16, %2;\n"      \
                         :: "r"(dst), "l"(src), "r"(sz));                       \
        }                                                                       \
        _Pragma("unroll")                                                       \
        for (int j = 0; j < BCH; j++) {                                         \
            int f = tid + j * NT;                                               \
            int n = f >> 2, c = (f & 3) << 3;                                   \
            const uint16_t* src = Wt + (size_t)(n0 + n) * K + k0 + c;           \
            uint32_t dst = (uint32_t)__cvta_generic_to_shared(&Bs[buf][n][c]);  \
            asm volatile("cp.async.cg.shared.global [%0], [%1], 16;\n"          \
                         :: "r"(dst), "l"(src));                                \
        }                                                                       \
        asm volatile("cp.async.commit_group;\n");                               \
    }

    ISSUE(0, 0);
    ISSUE(1, 1);
    asm volatile("cp.async.wait_group 1;\n");
    __syncthreads();

    const int r  = lane >> 2;
    const int c0 = (lane & 3) * 2;

    for (int t = 0; t < T; t++) {
        const int buf = t & 1;
        #pragma unroll
        for (int s = 0; s < 2; s++) {           // two k16 steps per BK=32
            const int kb = s * 16;
            uint32_t af[MT][4];
            #pragma unroll
            for (int mt = 0; mt < MT; mt++) {
                const uint16_t* pr0 = &As[buf][wm + mt*16 + r    ][kb + c0];
                const uint16_t* pr8 = &As[buf][wm + mt*16 + r + 8][kb + c0];
                af[mt][0] = *(const uint32_t*)pr0;
                af[mt][1] = *(const uint32_t*)pr8;
                af[mt][2] = *(const uint32_t*)(pr0 + 8);
                af[mt][3] = *(const uint32_t*)(pr8 + 8);
            }
            #pragma unroll
            for (int nt = 0; nt < NTL; nt++) {
                const uint16_t* pb = &Bs[buf][wn + nt*8 + r][kb + c0];
                uint32_t b0 = *(const uint32_t*)pb;
                uint32_t b1 = *(const uint32_t*)(pb + 8);
                #pragma unroll
                for (int mt = 0; mt < MT; mt++) {
                    asm volatile(
                        "mma.sync.aligned.m16n8k16.row.col.f32.bf16.bf16.f32 "
                        "{%0,%1,%2,%3},{%4,%5,%6,%7},{%8,%9},{%0,%1,%2,%3};\n"
                        : "+f"(acc[mt][nt][0]), "+f"(acc[mt][nt][1]),
                          "+f"(acc[mt][nt][2]), "+f"(acc[mt][nt][3])
                        : "r"(af[mt][0]), "r"(af[mt][1]),
                          "r"(af[mt][2]), "r"(af[mt][3]),
                          "r"(b0), "r"(b1));
                }
            }
        }
        __syncthreads();
        if (t + 2 < T) { ISSUE(t + 2, buf); }
        else           { asm volatile("cp.async.commit_group;\n"); }
        asm volatile("cp.async.wait_group 1;\n");
        __syncthreads();
    }
    #undef ISSUE

    #pragma unroll
    for (int mt = 0; mt < MT; mt++) {
        int r0 = m0 + wm + mt*16 + r;
        #pragma unroll
        for (int nt = 0; nt < NTL; nt++) {
            int cc = n0 + wn + nt*8 + c0;
            if (OUT == 2) {
                uint16_t* C8 = (uint16_t*)Cv;
                if (r0 < M)
                    C8[(size_t)r0 * (N/2) + cc/2] =
                        f2_to_fp8x2(acc[mt][nt][0], acc[mt][nt][1]);
                if (r0 + 8 < M)
                    C8[(size_t)(r0 + 8) * (N/2) + cc/2] =
                        f2_to_fp8x2(acc[mt][nt][2], acc[mt][nt][3]);
            } else {
                uint32_t* Cb = (uint32_t*)Cv;
                if (r0 < M)
                    Cb[(size_t)r0 * (N/2) + cc/2] =
                        f2_to_bf2x(acc[mt][nt][0], acc[mt][nt][1]);
                if (r0 + 8 < M)
                    Cb[(size_t)(r0 + 8) * (N/2) + cc/2] =
                        f2_to_bf2x(acc[mt][nt][2], acc[mt][nt][3]);
            }
        }
    }
}

// ---------------------------------------------------------------------------
// SpMM F=256 over fp8 support: 2 rows per 128-block, 64 threads/row,
// each thread covers 4 features (one u32 gather / edge).
// out = bf16( relu( sum val*sup[col] + bias ) )  (fp32 accumulate)
// ---------------------------------------------------------------------------
__global__ __launch_bounds__(128) void k_spmm256_f8(
    const uint32_t* __restrict__ sup8, const float* __restrict__ bias,
    uint32_t* __restrict__ out)
{
    int t64 = threadIdx.x & 63;
    int row = blockIdx.x * 2 + (threadIdx.x >> 6);
    int s = g_rowptr[row], e = g_rowptr[row + 1];

    float a0 = 0.f, a1 = 0.f, a2 = 0.f, a3 = 0.f;
    int i = s;
    for (; i + 4 <= e; i += 4) {
        int2 r0 = g_edge[i],     r1 = g_edge[i + 1];
        int2 r2 = g_edge[i + 2], r3 = g_edge[i + 3];
        uint32_t u0 = sup8[(size_t)r0.x * 64 + t64];
        uint32_t u1 = sup8[(size_t)r1.x * 64 + t64];
        uint32_t u2 = sup8[(size_t)r2.x * 64 + t64];
        uint32_t u3 = sup8[(size_t)r3.x * 64 + t64];
        float v0 = __int_as_float(r0.y), v1 = __int_as_float(r1.y);
        float v2 = __int_as_float(r2.y), v3 = __int_as_float(r3.y);
        {
            float2 lo = fp8x2_to_f2((uint16_t)(u0 & 0xffff));
            float2 hi = fp8x2_to_f2((uint16_t)(u0 >> 16));
            a0 = fmaf(v0, lo.x, a0); a1 = fmaf(v0, lo.y, a1);
            a2 = fmaf(v0, hi.x, a2); a3 = fmaf(v0, hi.y, a3);
        }
        {
            float2 lo = fp8x2_to_f2((uint16_t)(u1 & 0xffff));
            float2 hi = fp8x2_to_f2((uint16_t)(u1 >> 16));
            a0 = fmaf(v1, lo.x, a0); a1 = fmaf(v1, lo.y, a1);
            a2 = fmaf(v1, hi.x, a2); a3 = fmaf(v1, hi.y, a3);
        }
        {
            float2 lo = fp8x2_to_f2((uint16_t)(u2 & 0xffff));
            float2 hi = fp8x2_to_f2((uint16_t)(u2 >> 16));
            a0 = fmaf(v2, lo.x, a0); a1 = fmaf(v2, lo.y, a1);
            a2 = fmaf(v2, hi.x, a2); a3 = fmaf(v2, hi.y, a3);
        }
        {
            float2 lo = fp8x2_to_f2((uint16_t)(u3 & 0xffff));
            float2 hi = fp8x2_to_f2((uint16_t)(u3 >> 16));
            a0 = fmaf(v3, lo.x, a0); a1 = fmaf(v3, lo.y, a1);
            a2 = fmaf(v3, hi.x, a2); a3 = fmaf(v3, hi.y, a3);
        }
    }
    for (; i < e; i++) {
        int2 r = g_edge[i];
        float v = __int_as_float(r.y);
        uint32_t u = sup8[(size_t)r.x * 64 + t64];
        float2 lo = fp8x2_to_f2((uint16_t)(u & 0xffff));
        float2 hi = fp8x2_to_f2((uint16_t)(u >> 16));
        a0 = fmaf(v, lo.x, a0); a1 = fmaf(v, lo.y, a1);
        a2 = fmaf(v, hi.x, a2); a3 = fmaf(v, hi.y, a3);
    }
    float4 b = *(const float4*)&bias[4 * t64];
    uint2 o;
    o.x = f2_to_bf2x(fmaxf(a0 + b.x, 0.f), fmaxf(a1 + b.y, 0.f));
    o.y = f2_to_bf2x(fmaxf(a2 + b.z, 0.f), fmaxf(a3 + b.w, 0.f));
    *(uint2*)&out[(size_t)row * 128 + 2 * t64] = o;
}

// ---------------------------------------------------------------------------
// SpMM F=64 over fp8 support + bias + log_softmax. Warp per row, 4 rows/block.
// Each lane gathers one fp8x2 (2 B) per edge -> 64 B/edge total.
// ---------------------------------------------------------------------------
__global__ __launch_bounds__(128) void k_spmm64_lsm_f8(
    const uint16_t* __restrict__ sup8, const float* __restrict__ b3,
    float* __restrict__ out)
{
    int lane = threadIdx.x & 31;
    int row  = blockIdx.x * 4 + (threadIdx.x >> 5);

    int s = g_rowptr[row], e = g_rowptr[row + 1];

    float ax0 = 0.f, ay0 = 0.f, ax1 = 0.f, ay1 = 0.f;
    int i = s;
    for (; i + 4 <= e; i += 4) {
        int2 r0 = g_edge[i],     r1 = g_edge[i + 1];
        int2 r2 = g_edge[i + 2], r3 = g_edge[i + 3];
        uint16_t u0 = sup8[(size_t)r0.x * 32 + lane];
        uint16_t u1 = sup8[(size_t)r1.x * 32 + lane];
        uint16_t u2 = sup8[(size_t)r2.x * 32 + lane];
        uint16_t u3 = sup8[(size_t)r3.x * 32 + lane];
        float2 f0 = fp8x2_to_f2(u0);
        float2 f1 = fp8x2_to_f2(u1);
        float2 f2 = fp8x2_to_f2(u2);
        float2 f3 = fp8x2_to_f2(u3);
        float v0 = __int_as_float(r0.y), v1 = __int_as_float(r1.y);
        float v2 = __int_as_float(r2.y), v3 = __int_as_float(r3.y);
        ax0 = fmaf(v0, f0.x, ax0); ay0 = fmaf(v0, f0.y, ay0);
        ax1 = fmaf(v1, f1.x, ax1); ay1 = fmaf(v1, f1.y, ay1);
        ax0 = fmaf(v2, f2.x, ax0); ay0 = fmaf(v2, f2.y, ay0);
        ax1 = fmaf(v3, f3.x, ax1); ay1 = fmaf(v3, f3.y, ay1);
    }
    for (; i < e; i++) {
        int2 r = g_edge[i];
        float v = __int_as_float(r.y);
        float2 f = fp8x2_to_f2(sup8[(size_t)r.x * 32 + lane]);
        ax0 = fmaf(v, f.x, ax0); ay0 = fmaf(v, f.y, ay0);
    }
    float2 b = *(const float2*)&b3[2 * lane];
    float rx = ax0 + ax1 + b.x;
    float ry = ay0 + ay1 + b.y;

    // warp log-softmax over 64 values (2 per lane)
    float m = fmaxf(rx, ry);
    #pragma unroll
    for (int o = 16; o > 0; o >>= 1)
        m = fmaxf(m, __shfl_xor_sync(0xFFFFFFFFu, m, o));
    float sum = expf(rx - m) + expf(ry - m);
    #pragma unroll
    for (int o = 16; o > 0; o >>= 1)
        sum += __shfl_xor_sync(0xFFFFFFFFu, sum, o);
    float ls = m + logf(sum);

    float2 o2 = make_float2(rx - ls, ry - ls);
    *(float2*)&out[(size_t)row * 64 + 2 * lane] = o2;
}

// ---------------------------------------------------------------------------
// Launch — fork pure-CSR side stream under cvt+GEMM1; fp8 layer-3 support.
// ---------------------------------------------------------------------------
extern "C" void kernel_launch(void* const* d_in, const int* in_sizes, int n_in,
                              void* d_out, int out_size)
{
    const float* x    = (const float*)d_in[0];
    const int*   erow = (const int*)  d_in[1];
    const int*   ecol = (const int*)  d_in[2];
    const float* eval = (const float*)d_in[3];
    const float* W1   = (const float*)d_in[4];
    const float* b1   = (const float*)d_in[5];
    const float* W2   = (const float*)d_in[6];
    const float* b2   = (const float*)d_in[7];
    const float* W3   = (const float*)d_in[8];
    const float* b3   = (const float*)d_in[9];
    float* out = (float*)d_out;

    uint16_t *dW1t, *dW2t, *dW3t, *dC8;
    uint32_t *dS8, *dHbf;
    int *dCur;
    cudaGetSymbolAddress((void**)&dS8,  g_S8);
    cudaGetSymbolAddress((void**)&dHbf, g_Hbf);
    cudaGetSymbolAddress((void**)&dC8,  g_C8);
    cudaGetSymbolAddress((void**)&dW1t, g_W1t);
    cudaGetSymbolAddress((void**)&dW2t, g_W2t);
    cudaGetSymbolAddress((void**)&dW3t, g_W3t);
    cudaGetSymbolAddress((void**)&dCur, g_cursor);

    // one-time host resources (created on the uncaptured correctness call,
    // reused under capture; launched work is identical every call)
    static cudaStream_t s_side = nullptr;
    static cudaEvent_t  evFork = nullptr, evJoin = nullptr;
    if (!s_side) {
        cudaStreamCreateWithFlags(&s_side, cudaStreamNonBlocking);
        cudaEventCreateWithFlags(&evFork, cudaEventDisableTiming);
        cudaEventCreateWithFlags(&evJoin, cudaEventDisableTiming);
    }

    const int NB_SCAN = (NN + 1 + 1023) / 1024;
    const int EB = (EE + 255) / 256;
    const int MB = (NN + 127) / 128;

    // ---- fork: side stream = CSR build ONLY (join gates spmm1 asap) ----
    cudaEventRecord(evFork, 0);
    cudaStreamWaitEvent(s_side, evFork, 0);

    k_zero_int<<<(NN + 255) / 256, 256, 0, s_side>>>(dCur, NN);
    k_hist<<<EB, 256, 0, s_side>>>(erow);
    k_scan_block<<<NB_SCAN, 1024, 0, s_side>>>(NN + 1);
    k_scan_spine<<<1, 128, 0, s_side>>>(NB_SCAN);
    k_scan_add<<<NB_SCAN, 1024, 0, s_side>>>(NN + 1);   // also seeds cursor
    k_scatter<<<EB, 256, 0, s_side>>>(erow, ecol, eval);
    cudaEventRecord(evJoin, s_side);

    // main stream: all W cvts + GEMM1 (fused fp32->bf16 A conversion)
    k_cvt_wt<<<(F0*F1 + 255) / 256, 256>>>(W1, dW1t, F0, F1);
    k_cvt_wt<<<(F1*F2 + 255) / 256, 256>>>(W2, dW2t, F1, F2);
    k_cvt_wt<<<(F2*F3 + 255) / 256, 256>>>(W3, dW3t, F2, F3);
    k_gemm_f32a<<<dim3(F1/128, MB), 128>>>(x, dW1t, (uint16_t*)dS8, NN, F1, F0);

    // ---- join: spmm needs CSR ----
    cudaStreamWaitEvent(0, evJoin, 0);

    // layer 1 aggregate
    k_spmm256_f8<<<NN/2, 128>>>(dS8, b1, dHbf);

    // layer 2
    k_gemm_bf<128,128,64,64,2><<<dim3(F2/128, MB), 128>>>((const uint16_t*)dHbf, dW2t, dS8, NN, F2, F1);
    k_spmm256_f8<<<NN/2, 128>>>(dS8, b2, dHbf);

    // layer 3 (fp8 support) + log_softmax
    k_gemm_bf<128,64,64,32,2><<<dim3(F3/64, MB), 128>>>((const uint16_t*)dHbf, dW3t, dC8, NN, F3, F2);
    k_spmm64_lsm_f8<<<NN/4, 128>>>(dC8, b3, out);
}

// round 17
// speedup vs baseline: 1.1121x; 1.1121x over previous
#include <cuda_runtime.h>
#include <cuda_bf16.h>
#include <cuda_fp16.h>
#include <math.h>
#include <stdint.h>

// ---------------------------------------------------------------------------
// Problem constants
// ---------------------------------------------------------------------------
#define NN 100000
#define EE 3200000
#define F0 512
#define F1 256
#define F2 256
#define F3 64

// ---------------------------------------------------------------------------
// Scratch (__device__ globals; no allocations allowed)
// ---------------------------------------------------------------------------
__device__ uint32_t g_S8 [(size_t)NN * 64];    // fp8(e4m3) support, F=256 (25.6 MB)
__device__ uint32_t g_Hbf[(size_t)NN * 128];   // bf16x2 activations, F=256 (51.2 MB)
__device__ uint32_t g_Cbf[(size_t)NN * 32];    // bf16x2 support, F=64
__device__ uint16_t g_W1t[F1 * F0];            // Wt[N][K] bf16 (transposed)
__device__ uint16_t g_W2t[F2 * F1];
__device__ uint16_t g_W3t[F3 * F2];
__device__ int      g_rowptr[NN + 1];
__device__ int      g_cursor[NN];
__device__ int2     g_edge[EE];                // packed (col, val-bits)
__device__ int      g_bsums[128];

// bf16x2 -> two fp32 (exact, pure ALU)
__device__ __forceinline__ float2 bf2x_to_f2(uint32_t u) {
    float2 f;
    f.x = __uint_as_float(u << 16);
    f.y = __uint_as_float(u & 0xffff0000u);
    return f;
}
// 2x e4m3 (packed u16) -> float2 via half2
__device__ __forceinline__ float2 fp8x2_to_f2(uint16_t p) {
    uint32_t h;
    asm("cvt.rn.f16x2.e4m3x2 %0, %1;" : "=r"(h) : "h"(p));
    return __half22float2(*(__half2*)&h);
}
__device__ __forceinline__ uint16_t f2_to_fp8x2(float lo, float hi) {
    uint16_t p;
    asm("cvt.rn.satfinite.e4m3x2.f32 %0, %1, %2;" : "=h"(p) : "f"(hi), "f"(lo));
    return p;  // low byte = lo
}
__device__ __forceinline__ uint32_t f2_to_bf2x(float lo, float hi) {
    __nv_bfloat162 p = __floats2bfloat162_rn(lo, hi);
    return *(uint32_t*)&p;
}

// ---------------------------------------------------------------------------
// Weight conversion: W[K][N] fp32 -> Wt[N][K] bf16
// ---------------------------------------------------------------------------
__global__ void k_cvt_wt(const float* __restrict__ W, uint16_t* __restrict__ Wt, int K, int N) {
    int i = blockIdx.x * blockDim.x + threadIdx.x;
    if (i < K * N) {
        int k = i / N, n = i % N;
        __nv_bfloat16 b = __float2bfloat16(W[i]);
        Wt[(size_t)n * K + k] = *(uint16_t*)&b;
    }
}

// ---------------------------------------------------------------------------
// CSR build: histogram -> exclusive scan -> scatter (packed records)
// ---------------------------------------------------------------------------
__global__ void k_zero_int(int* p, int n) {
    int i = blockIdx.x * blockDim.x + threadIdx.x;
    if (i < n) p[i] = 0;
}

__global__ void k_hist(const int* __restrict__ erow) {
    int e = blockIdx.x * blockDim.x + threadIdx.x;
    if (e < EE) atomicAdd(&g_cursor[erow[e]], 1);
}

__global__ void k_scan_block(int n) {
    int tid  = threadIdx.x;
    int i    = blockIdx.x * 1024 + tid;
    int v    = (i < NN) ? g_cursor[i] : 0;
    int lane = tid & 31, warp = tid >> 5;
    int x = v;
    #pragma unroll
    for (int o = 1; o < 32; o <<= 1) {
        int y = __shfl_up_sync(0xFFFFFFFFu, x, o);
        if (lane >= o) x += y;
    }
    __shared__ int wsum[32];
    if (lane == 31) wsum[warp] = x;
    __syncthreads();
    if (warp == 0) {
        int w = wsum[lane];
        #pragma unroll
        for (int o = 1; o < 32; o <<= 1) {
            int y = __shfl_up_sync(0xFFFFFFFFu, w, o);
            if (lane >= o) w += y;
        }
        wsum[lane] = w;
    }
    __syncthreads();
    int incl = x + (warp > 0 ? wsum[warp - 1] : 0);
    if (i < n) g_rowptr[i] = incl - v;
    if (tid == 1023) g_bsums[blockIdx.x] = incl;
}

__global__ void k_scan_spine(int nb) {
    int tid = threadIdx.x;
    int lane = tid & 31, warp = tid >> 5;
    int v = (tid < nb) ? g_bsums[tid] : 0;
    int x = v;
    #pragma unroll
    for (int o = 1; o < 32; o <<= 1) {
        int y = __shfl_up_sync(0xFFFFFFFFu, x, o);
        if (lane >= o) x += y;
    }
    __shared__ int ws[4];
    if (lane == 31) ws[warp] = x;
    __syncthreads();
    int off = 0;
    for (int w = 0; w < warp; w++) off += ws[w];
    if (tid < nb) g_bsums[tid] = (x + off) - v;
}

// adds block offsets; also seeds cursor = rowptr for the scatter pass
__global__ void k_scan_add(int n) {
    int i = blockIdx.x * 1024 + threadIdx.x;
    if (i < n) {
        int v = g_rowptr[i] + g_bsums[blockIdx.x];
        g_rowptr[i] = v;
        if (i < NN) g_cursor[i] = v;
    }
}

__global__ void k_scatter(const int* __restrict__ erow,
                          const int* __restrict__ ecol,
                          const float* __restrict__ eval) {
    int e = blockIdx.x * blockDim.x + threadIdx.x;
    if (e < EE) {
        int r = erow[e];
        int p = atomicAdd(&g_cursor[r], 1);
        int2 rec;
        rec.x = ecol[e];
        rec.y = __float_as_int(eval[e]);
        g_edge[p] = rec;
    }
}

// ---------------------------------------------------------------------------
// GEMM1: C = fp8( A_fp32[M,K] @ Wt[N,K]^T ), A converted to bf16 in-register.
// 128x128 tile, 4 warps (64x64 each), BK=16, cp.async.cg double-buffered.
// ---------------------------------------------------------------------------
__global__ __launch_bounds__(128) void k_gemm_f32a(
    const float* __restrict__ A, const uint16_t* __restrict__ Wt,
    uint16_t* __restrict__ C8, int M, int N, int K)
{
    constexpr int BM = 128, BN = 128, BK = 16;
    constexpr int NT = 128;
    constexpr int ASTF = BK + 8;   // 24 floats  (LDS.64 conflict-free)
    constexpr int BST  = BK + 8;   // 24 bf16
    constexpr int MT = 4, NTL = 8;

    __shared__ __align__(16) float    Asf[2][BM][ASTF];
    __shared__ __align__(16) uint16_t Bs [2][BN][BST];

    const int tid = threadIdx.x;
    const int lane = tid & 31, wid = tid >> 5;
    const int wm = (wid % 2) * 64;
    const int wn = (wid / 2) * 64;
    const int m0 = blockIdx.y * BM, n0 = blockIdx.x * BN;

    float acc[MT][NTL][4];
    #pragma unroll
    for (int i = 0; i < MT; i++)
        #pragma unroll
        for (int j = 0; j < NTL; j++)
            #pragma unroll
            for (int q = 0; q < 4; q++) acc[i][j][q] = 0.f;

    const int T = K / BK;

    #define ISSUE1(t, buf)                                                      \
    {                                                                           \
        int k0 = (t) * BK;                                                      \
        _Pragma("unroll")                                                       \
        for (int j = 0; j < 4; j++) {          /* A: 128x16 fp32, 4 f4/thr */   \
            int f = tid + j * NT;                                               \
            int m = f >> 2, c = (f & 3) << 2;                                   \
            int gm = m0 + m;                                                    \
            const float* src = A + (size_t)(gm < M ? gm : 0) * K + k0 + c;      \
            uint32_t dst = (uint32_t)__cvta_generic_to_shared(&Asf[buf][m][c]); \
            int sz = (gm < M) ? 16 : 0;                                         \
            asm volatile("cp.async.cg.shared.global [%0], [%1], 16, %2;\n"      \
                         :: "r"(dst), "l"(src), "r"(sz));                       \
        }                                                                       \
        _Pragma("unroll")                                                       \
        for (int j = 0; j < 2; j++) {          /* B: 128x16 bf16, 2 16B/thr */  \
            int f = tid + j * NT;                                               \
            int n = f >> 1, c = (f & 1) << 3;                                   \
            const uint16_t* src = Wt + (size_t)(n0 + n) * K + k0 + c;           \
            uint32_t dst = (uint32_t)__cvta_generic_to_shared(&Bs[buf][n][c]);  \
            asm volatile("cp.async.cg.shared.global [%0], [%1], 16;\n"          \
                         :: "r"(dst), "l"(src));                                \
        }                                                                       \
        asm volatile("cp.async.commit_group;\n");                               \
    }

    ISSUE1(0, 0);
    ISSUE1(1, 1);
    asm volatile("cp.async.wait_group 1;\n");
    __syncthreads();

    const int r  = lane >> 2;
    const int c0 = (lane & 3) * 2;

    for (int t = 0; t < T; t++) {
        const int buf = t & 1;
        uint32_t af[MT][4];
        #pragma unroll
        for (int mt = 0; mt < MT; mt++) {
            float2 p0 = *(const float2*)&Asf[buf][wm + mt*16 + r    ][c0    ];
            float2 p1 = *(const float2*)&Asf[buf][wm + mt*16 + r + 8][c0    ];
            float2 p2 = *(const float2*)&Asf[buf][wm + mt*16 + r    ][c0 + 8];
            float2 p3 = *(const float2*)&Asf[buf][wm + mt*16 + r + 8][c0 + 8];
            af[mt][0] = f2_to_bf2x(p0.x, p0.y);
            af[mt][1] = f2_to_bf2x(p1.x, p1.y);
            af[mt][2] = f2_to_bf2x(p2.x, p2.y);
            af[mt][3] = f2_to_bf2x(p3.x, p3.y);
        }
        #pragma unroll
        for (int nt = 0; nt < NTL; nt++) {
            const uint16_t* pb = &Bs[buf][wn + nt*8 + r][c0];
            uint32_t b0 = *(const uint32_t*)pb;
            uint32_t b1 = *(const uint32_t*)(pb + 8);
            #pragma unroll
            for (int mt = 0; mt < MT; mt++) {
                asm volatile(
                    "mma.sync.aligned.m16n8k16.row.col.f32.bf16.bf16.f32 "
                    "{%0,%1,%2,%3},{%4,%5,%6,%7},{%8,%9},{%0,%1,%2,%3};\n"
                    : "+f"(acc[mt][nt][0]), "+f"(acc[mt][nt][1]),
                      "+f"(acc[mt][nt][2]), "+f"(acc[mt][nt][3])
                    : "r"(af[mt][0]), "r"(af[mt][1]),
                      "r"(af[mt][2]), "r"(af[mt][3]),
                      "r"(b0), "r"(b1));
            }
        }
        __syncthreads();
        if (t + 2 < T) { ISSUE1(t + 2, buf); }
        else           { asm volatile("cp.async.commit_group;\n"); }
        asm volatile("cp.async.wait_group 1;\n");
        __syncthreads();
    }
    #undef ISSUE1

    #pragma unroll
    for (int mt = 0; mt < MT; mt++) {
        int r0 = m0 + wm + mt*16 + r;
        #pragma unroll
        for (int nt = 0; nt < NTL; nt++) {
            int cc = n0 + wn + nt*8 + c0;
            if (r0 < M)
                C8[(size_t)r0 * (N/2) + cc/2] =
                    f2_to_fp8x2(acc[mt][nt][0], acc[mt][nt][1]);
            if (r0 + 8 < M)
                C8[(size_t)(r0 + 8) * (N/2) + cc/2] =
                    f2_to_fp8x2(acc[mt][nt][2], acc[mt][nt][3]);
        }
    }
}

// ---------------------------------------------------------------------------
// BF16 tensor-core GEMM: C[M,N] = A[M,K] @ Wt[N,K]^T  (A already bf16)
// mma.sync.m16n8k16.bf16, cp.async.cg double-buffered, 80B-stride.
// OUT: 1 = bf16x2 packed, 2 = e4m3 packed.
// ---------------------------------------------------------------------------
template<int BM, int BN, int WM, int WN, int OUT>
__global__ __launch_bounds__((BM/WM)*(BN/WN)*32) void k_gemm_bf(
    const uint16_t* __restrict__ A, const uint16_t* __restrict__ Wt,
    void* __restrict__ Cv, int M, int N, int K)
{
    constexpr int BK  = 32;
    constexpr int NWARP = (BM/WM)*(BN/WN);
    constexpr int NT  = NWARP * 32;
    constexpr int ST  = BK + 8;            // 40 bf16 = 80 B row stride
    constexpr int ACH = BM*BK/8/NT;
    constexpr int BCH = BN*BK/8/NT;
    constexpr int MT  = WM/16, NTL = WN/8;

    __shared__ uint16_t As[2][BM][ST];
    __shared__ uint16_t Bs[2][BN][ST];

    const int tid  = threadIdx.x;
    const int lane = tid & 31, wid = tid >> 5;
    const int wm   = (wid % (BM/WM)) * WM;
    const int wn   = (wid / (BM/WM)) * WN;
    const int m0   = blockIdx.y * BM, n0 = blockIdx.x * BN;

    float acc[MT][NTL][4];
    #pragma unroll
    for (int i = 0; i < MT; i++)
        #pragma unroll
        for (int j = 0; j < NTL; j++)
            #pragma unroll
            for (int q = 0; q < 4; q++) acc[i][j][q] = 0.f;

    const int T = K / BK;

    #define ISSUE(t, buf)                                                       \
    {                                                                           \
        int k0 = (t) * BK;                                                      \
        _Pragma("unroll")                                                       \
        for (int j = 0; j < ACH; j++) {                                         \
            int f = tid + j * NT;                                               \
            int m = f >> 2, c = (f & 3) << 3;                                   \
            int gm = m0 + m;                                                    \
            const uint16_t* src = A + (size_t)(gm < M ? gm : 0) * K + k0 + c;   \
            uint32_t dst = (uint32_t)__cvta_generic_to_shared(&As[buf][m][c]);  \
            int sz = (gm < M) ? 16 : 0;                                         \
            asm volatile("cp.async.cg.shared.global [%0], [%1], 16, %2;\n"      \
                         :: "r"(dst), "l"(src), "r"(sz));                       \
        }                                                                       \
        _Pragma("unroll")                                                       \
        for (int j = 0; j < BCH; j++) {                                         \
            int f = tid + j * NT;                                               \
            int n = f >> 2, c = (f & 3) << 3;                                   \
            const uint16_t* src = Wt + (size_t)(n0 + n) * K + k0 + c;           \
            uint32_t dst = (uint32_t)__cvta_generic_to_shared(&Bs[buf][n][c]);  \
            asm volatile("cp.async.cg.shared.global [%0], [%1], 16;\n"          \
                         :: "r"(dst), "l"(src));                                \
        }                                                                       \
        asm volatile("cp.async.commit_group;\n");                               \
    }

    ISSUE(0, 0);
    ISSUE(1, 1);
    asm volatile("cp.async.wait_group 1;\n");
    __syncthreads();

    const int r  = lane >> 2;
    const int c0 = (lane & 3) * 2;

    for (int t = 0; t < T; t++) {
        const int buf = t & 1;
        #pragma unroll
        for (int s = 0; s < 2; s++) {           // two k16 steps per BK=32
            const int kb = s * 16;
            uint32_t af[MT][4];
            #pragma unroll
            for (int mt = 0; mt < MT; mt++) {
                const uint16_t* pr0 = &As[buf][wm + mt*16 + r    ][kb + c0];
                const uint16_t* pr8 = &As[buf][wm + mt*16 + r + 8][kb + c0];
                af[mt][0] = *(const uint32_t*)pr0;
                af[mt][1] = *(const uint32_t*)pr8;
                af[mt][2] = *(const uint32_t*)(pr0 + 8);
                af[mt][3] = *(const uint32_t*)(pr8 + 8);
            }
            #pragma unroll
            for (int nt = 0; nt < NTL; nt++) {
                const uint16_t* pb = &Bs[buf][wn + nt*8 + r][kb + c0];
                uint32_t b0 = *(const uint32_t*)pb;
                uint32_t b1 = *(const uint32_t*)(pb + 8);
                #pragma unroll
                for (int mt = 0; mt < MT; mt++) {
                    asm volatile(
                        "mma.sync.aligned.m16n8k16.row.col.f32.bf16.bf16.f32 "
                        "{%0,%1,%2,%3},{%4,%5,%6,%7},{%8,%9},{%0,%1,%2,%3};\n"
                        : "+f"(acc[mt][nt][0]), "+f"(acc[mt][nt][1]),
                          "+f"(acc[mt][nt][2]), "+f"(acc[mt][nt][3])
                        : "r"(af[mt][0]), "r"(af[mt][1]),
                          "r"(af[mt][2]), "r"(af[mt][3]),
                          "r"(b0), "r"(b1));
                }
            }
        }
        __syncthreads();
        if (t + 2 < T) { ISSUE(t + 2, buf); }
        else           { asm volatile("cp.async.commit_group;\n"); }
        asm volatile("cp.async.wait_group 1;\n");
        __syncthreads();
    }
    #undef ISSUE

    #pragma unroll
    for (int mt = 0; mt < MT; mt++) {
        int r0 = m0 + wm + mt*16 + r;
        #pragma unroll
        for (int nt = 0; nt < NTL; nt++) {
            int cc = n0 + wn + nt*8 + c0;
            if (OUT == 2) {
                uint16_t* C8 = (uint16_t*)Cv;
                if (r0 < M)
                    C8[(size_t)r0 * (N/2) + cc/2] =
                        f2_to_fp8x2(acc[mt][nt][0], acc[mt][nt][1]);
                if (r0 + 8 < M)
                    C8[(size_t)(r0 + 8) * (N/2) + cc/2] =
                        f2_to_fp8x2(acc[mt][nt][2], acc[mt][nt][3]);
            } else {
                uint32_t* Cb = (uint32_t*)Cv;
                if (r0 < M)
                    Cb[(size_t)r0 * (N/2) + cc/2] =
                        f2_to_bf2x(acc[mt][nt][0], acc[mt][nt][1]);
                if (r0 + 8 < M)
                    Cb[(size_t)(r0 + 8) * (N/2) + cc/2] =
                        f2_to_bf2x(acc[mt][nt][2], acc[mt][nt][3]);
            }
        }
    }
}

// ---------------------------------------------------------------------------
// SpMM F=256 over fp8 support: WARP per row (4 rows / 128-block),
// each lane gathers uint2 = 8 fp8 features per edge (one 8B LDG).
// Halves LSU issue count vs 64-thread/row version; same bytes.
// out = bf16( relu( sum val*sup[col] + bias ) )  (fp32 accumulate)
// ---------------------------------------------------------------------------
__global__ __launch_bounds__(128) void k_spmm256_f8(
    const uint2* __restrict__ sup8, const float* __restrict__ bias,
    uint32_t* __restrict__ out)
{
    int lane = threadIdx.x & 31;
    int row  = blockIdx.x * 4 + (threadIdx.x >> 5);
    int s = g_rowptr[row], e = g_rowptr[row + 1];

    float a[8];
    #pragma unroll
    for (int q = 0; q < 8; q++) a[q] = 0.f;

    #define ACC_EDGE(u, v)                                                     \
    {                                                                          \
        float2 f0 = fp8x2_to_f2((uint16_t)((u).x & 0xffff));                   \
        float2 f1 = fp8x2_to_f2((uint16_t)((u).x >> 16));                      \
        float2 f2 = fp8x2_to_f2((uint16_t)((u).y & 0xffff));                   \
        float2 f3 = fp8x2_to_f2((uint16_t)((u).y >> 16));                      \
        a[0] = fmaf((v), f0.x, a[0]); a[1] = fmaf((v), f0.y, a[1]);            \
        a[2] = fmaf((v), f1.x, a[2]); a[3] = fmaf((v), f1.y, a[3]);            \
        a[4] = fmaf((v), f2.x, a[4]); a[5] = fmaf((v), f2.y, a[5]);            \
        a[6] = fmaf((v), f3.x, a[6]); a[7] = fmaf((v), f3.y, a[7]);            \
    }

    int i = s;
    for (; i + 4 <= e; i += 4) {
        int2 r0 = g_edge[i],     r1 = g_edge[i + 1];
        int2 r2 = g_edge[i + 2], r3 = g_edge[i + 3];
        uint2 u0 = sup8[(size_t)r0.x * 32 + lane];
        uint2 u1 = sup8[(size_t)r1.x * 32 + lane];
        uint2 u2 = sup8[(size_t)r2.x * 32 + lane];
        uint2 u3 = sup8[(size_t)r3.x * 32 + lane];
        float v0 = __int_as_float(r0.y), v1 = __int_as_float(r1.y);
        float v2 = __int_as_float(r2.y), v3 = __int_as_float(r3.y);
        ACC_EDGE(u0, v0);
        ACC_EDGE(u1, v1);
        ACC_EDGE(u2, v2);
        ACC_EDGE(u3, v3);
    }
    for (; i < e; i++) {
        int2 r = g_edge[i];
        float v = __int_as_float(r.y);
        uint2 u = sup8[(size_t)r.x * 32 + lane];
        ACC_EDGE(u, v);
    }
    #undef ACC_EDGE

    float4 b0 = *(const float4*)&bias[8 * lane];
    float4 b1 = *(const float4*)&bias[8 * lane + 4];
    uint4 o;
    o.x = f2_to_bf2x(fmaxf(a[0] + b0.x, 0.f), fmaxf(a[1] + b0.y, 0.f));
    o.y = f2_to_bf2x(fmaxf(a[2] + b0.z, 0.f), fmaxf(a[3] + b0.w, 0.f));
    o.z = f2_to_bf2x(fmaxf(a[4] + b1.x, 0.f), fmaxf(a[5] + b1.y, 0.f));
    o.w = f2_to_bf2x(fmaxf(a[6] + b1.z, 0.f), fmaxf(a[7] + b1.w, 0.f));
    *(uint4*)&out[(size_t)row * 128 + 4 * lane] = o;
}

// ---------------------------------------------------------------------------
// SpMM F=64 (bf16 support) + bias + log_softmax. Warp per row, 4 rows/block.
// ---------------------------------------------------------------------------
__global__ __launch_bounds__(128) void k_spmm64_lsm_bf(
    const uint32_t* __restrict__ supu, const float* __restrict__ b3,
    float* __restrict__ out)
{
    int lane = threadIdx.x & 31;
    int row  = blockIdx.x * 4 + (threadIdx.x >> 5);

    int s = g_rowptr[row], e = g_rowptr[row + 1];

    float ax0 = 0.f, ay0 = 0.f, ax1 = 0.f, ay1 = 0.f;
    int i = s;
    for (; i + 4 <= e; i += 4) {
        int2 r0 = g_edge[i],     r1 = g_edge[i + 1];
        int2 r2 = g_edge[i + 2], r3 = g_edge[i + 3];
        float2 f0 = bf2x_to_f2(supu[(size_t)r0.x * 32 + lane]);
        float2 f1 = bf2x_to_f2(supu[(size_t)r1.x * 32 + lane]);
        float2 f2 = bf2x_to_f2(supu[(size_t)r2.x * 32 + lane]);
        float2 f3 = bf2x_to_f2(supu[(size_t)r3.x * 32 + lane]);
        float v0 = __int_as_float(r0.y), v1 = __int_as_float(r1.y);
        float v2 = __int_as_float(r2.y), v3 = __int_as_float(r3.y);
        ax0 = fmaf(v0, f0.x, ax0); ay0 = fmaf(v0, f0.y, ay0);
        ax1 = fmaf(v1, f1.x, ax1); ay1 = fmaf(v1, f1.y, ay1);
        ax0 = fmaf(v2, f2.x, ax0); ay0 = fmaf(v2, f2.y, ay0);
        ax1 = fmaf(v3, f3.x, ax1); ay1 = fmaf(v3, f3.y, ay1);
    }
    for (; i < e; i++) {
        int2 r = g_edge[i];
        float v = __int_as_float(r.y);
        float2 f = bf2x_to_f2(supu[(size_t)r.x * 32 + lane]);
        ax0 = fmaf(v, f.x, ax0); ay0 = fmaf(v, f.y, ay0);
    }
    float2 b = *(const float2*)&b3[2 * lane];
    float rx = ax0 + ax1 + b.x;
    float ry = ay0 + ay1 + b.y;

    // warp log-softmax over 64 values (2 per lane)
    float m = fmaxf(rx, ry);
    #pragma unroll
    for (int o = 16; o > 0; o >>= 1)
        m = fmaxf(m, __shfl_xor_sync(0xFFFFFFFFu, m, o));
    float sum = expf(rx - m) + expf(ry - m);
    #pragma unroll
    for (int o = 16; o > 0; o >>= 1)
        sum += __shfl_xor_sync(0xFFFFFFFFu, sum, o);
    float ls = m + logf(sum);

    float2 o2 = make_float2(rx - ls, ry - ls);
    *(float2*)&out[(size_t)row * 64 + 2 * lane] = o2;
}

// ---------------------------------------------------------------------------
// Launch — fork pure-CSR side stream under cvt+GEMM1; bf16 layer-3 support.
// ---------------------------------------------------------------------------
extern "C" void kernel_launch(void* const* d_in, const int* in_sizes, int n_in,
                              void* d_out, int out_size)
{
    const float* x    = (const float*)d_in[0];
    const int*   erow = (const int*)  d_in[1];
    const int*   ecol = (const int*)  d_in[2];
    const float* eval = (const float*)d_in[3];
    const float* W1   = (const float*)d_in[4];
    const float* b1   = (const float*)d_in[5];
    const float* W2   = (const float*)d_in[6];
    const float* b2   = (const float*)d_in[7];
    const float* W3   = (const float*)d_in[8];
    const float* b3   = (const float*)d_in[9];
    float* out = (float*)d_out;

    uint16_t *dW1t, *dW2t, *dW3t;
    uint32_t *dS8, *dHbf, *dCbf;
    int *dCur;
    cudaGetSymbolAddress((void**)&dS8,  g_S8);
    cudaGetSymbolAddress((void**)&dHbf, g_Hbf);
    cudaGetSymbolAddress((void**)&dCbf, g_Cbf);
    cudaGetSymbolAddress((void**)&dW1t, g_W1t);
    cudaGetSymbolAddress((void**)&dW2t, g_W2t);
    cudaGetSymbolAddress((void**)&dW3t, g_W3t);
    cudaGetSymbolAddress((void**)&dCur, g_cursor);

    // one-time host resources (created on the uncaptured correctness call,
    // reused under capture; launched work is identical every call)
    static cudaStream_t s_side = nullptr;
    static cudaEvent_t  evFork = nullptr, evJoin = nullptr;
    if (!s_side) {
        cudaStreamCreateWithFlags(&s_side, cudaStreamNonBlocking);
        cudaEventCreateWithFlags(&evFork, cudaEventDisableTiming);
        cudaEventCreateWithFlags(&evJoin, cudaEventDisableTiming);
    }

    const int NB_SCAN = (NN + 1 + 1023) / 1024;
    const int EB = (EE + 255) / 256;
    const int MB = (NN + 127) / 128;

    // ---- fork: side stream = CSR build ONLY (join gates spmm1 asap) ----
    cudaEventRecord(evFork, 0);
    cudaStreamWaitEvent(s_side, evFork, 0);

    k_zero_int<<<(NN + 255) / 256, 256, 0, s_side>>>(dCur, NN);
    k_hist<<<EB, 256, 0, s_side>>>(erow);
    k_scan_block<<<NB_SCAN, 1024, 0, s_side>>>(NN + 1);
    k_scan_spine<<<1, 128, 0, s_side>>>(NB_SCAN);
    k_scan_add<<<NB_SCAN, 1024, 0, s_side>>>(NN + 1);   // also seeds cursor
    k_scatter<<<EB, 256, 0, s_side>>>(erow, ecol, eval);
    cudaEventRecord(evJoin, s_side);

    // main stream: all W cvts + GEMM1 (fused fp32->bf16 A conversion)
    k_cvt_wt<<<(F0*F1 + 255) / 256, 256>>>(W1, dW1t, F0, F1);
    k_cvt_wt<<<(F1*F2 + 255) / 256, 256>>>(W2, dW2t, F1, F2);
    k_cvt_wt<<<(F2*F3 + 255) / 256, 256>>>(W3, dW3t, F2, F3);
    k_gemm_f32a<<<dim3(F1/128, MB), 128>>>(x, dW1t, (uint16_t*)dS8, NN, F1, F0);

    // ---- join: spmm needs CSR ----
    cudaStreamWaitEvent(0, evJoin, 0);

    // layer 1 aggregate
    k_spmm256_f8<<<NN/4, 128>>>((const uint2*)dS8, b1, dHbf);

    // layer 2
    k_gemm_bf<128,128,64,64,2><<<dim3(F2/128, MB), 128>>>((const uint16_t*)dHbf, dW2t, dS8, NN, F2, F1);
    k_spmm256_f8<<<NN/4, 128>>>((const uint2*)dS8, b2, dHbf);

    // layer 3 (bf16 support) + log_softmax
    k_gemm_bf<128,64,64,32,1><<<dim3(F3/64, MB), 128>>>((const uint16_t*)dHbf, dW3t, dCbf, NN, F3, F2);
    k_spmm64_lsm_bf<<<NN/4, 128>>>(dCbf, b3, out);
}